// round 14
// baseline (speedup 1.0000x reference)
#include <cuda_runtime.h>

// Problem constants (fixed by the reference)
#define N_LAYERS 12
#define D_SAE    16384
#define D_MODEL  768
#define NNZ      131072

#define VEC      (D_MODEL / 4)   // 192 float4 per row
#define WARPS_PER_BLOCK 8
#define THREADS (WARPS_PER_BLOCK * 32)
#define ROWS_PER_WARP 2

// min-blocks=4 -> up to 64 regs/thread: room for a genuine 12x float4
// front-batch (48 regs) without ptxas collapsing it back to 6 live regs.
// Measured: regs=64, MLP=12, DRAM 78.7% — the mixed R/W HBM ceiling.
__global__ __launch_bounds__(THREADS, 4)
void gather_scale_kernel(const float4* __restrict__ W,      // [N_LAYERS*D_SAE, 192]
                         const float*  __restrict__ vals,   // [NNZ]
                         const int*    __restrict__ lidx,   // [NNZ]
                         const int*    __restrict__ fidx,   // [NNZ]
                         float4*       __restrict__ out)    // [NNZ, 192]
{
    const int warp_in_blk = threadIdx.x >> 5;
    const int lane        = threadIdx.x & 31;
    const int warp_id     = blockIdx.x * WARPS_PER_BLOCK + warp_in_blk;
    const int nz0         = warp_id * ROWS_PER_WARP;
    if (nz0 >= NNZ) return;
    const int nz1 = nz0 + 1;

    const float v0 = __ldg(&vals[nz0]);
    const float v1 = __ldg(&vals[nz1]);
    const long  row0 = (long)__ldg(&lidx[nz0]) * D_SAE + (long)__ldg(&fidx[nz0]);
    const long  row1 = (long)__ldg(&lidx[nz1]) * D_SAE + (long)__ldg(&fidx[nz1]);

    const float4* __restrict__ src0 = W   + row0 * (long)VEC;
    const float4* __restrict__ src1 = W   + row1 * (long)VEC;
    float4*       __restrict__ dst0 = out + (long)nz0 * (long)VEC;
    float4*       __restrict__ dst1 = out + (long)nz1 * (long)VEC;

    // Front-batch all 12 independent LDG.E.128 (2 rows x 6/lane) into
    // distinct registers: true per-warp read MLP = 12.
    float4 a[VEC / 32], b[VEC / 32];
    #pragma unroll
    for (int i = 0; i < VEC / 32; ++i) a[i] = __ldg(&src0[lane + i * 32]);
    #pragma unroll
    for (int i = 0; i < VEC / 32; ++i) b[i] = __ldg(&src1[lane + i * 32]);

    // Scale + evict-first stores (output stream is never re-read).
    #pragma unroll
    for (int i = 0; i < VEC / 32; ++i) {
        a[i].x *= v0; a[i].y *= v0; a[i].z *= v0; a[i].w *= v0;
        __stcs(&dst0[lane + i * 32], a[i]);
    }
    #pragma unroll
    for (int i = 0; i < VEC / 32; ++i) {
        b[i].x *= v1; b[i].y *= v1; b[i].z *= v1; b[i].w *= v1;
        __stcs(&dst1[lane + i * 32], b[i]);
    }
}

extern "C" void kernel_launch(void* const* d_in, const int* in_sizes, int n_in,
                              void* d_out, int out_size)
{
    // metadata order: W_D (f32), values (f32), layer_idx (i32), pos_idx (i32), feat_idx (i32)
    const float4* W    = (const float4*)d_in[0];
    const float*  vals = (const float*)d_in[1];
    const int*    lidx = (const int*)d_in[2];
    // pos_idx (d_in[3]) is unused by the reference computation
    const int*    fidx = (const int*)d_in[4];
    float4*       out  = (float4*)d_out;

    const int grid = NNZ / (WARPS_PER_BLOCK * ROWS_PER_WARP);   // 8192 blocks
    gather_scale_kernel<<<grid, THREADS>>>(W, vals, lidx, fidx, out);
}

// round 16
// speedup vs baseline: 1.0320x; 1.0320x over previous
#include <cuda_runtime.h>

// Problem constants (fixed by the reference)
#define N_LAYERS 12
#define D_SAE    16384
#define D_MODEL  768
#define NNZ      131072

#define VEC      (D_MODEL / 4)   // 192 float4 per row
#define WARPS_PER_BLOCK 8
#define THREADS (WARPS_PER_BLOCK * 32)

// Final configuration (session result):
//   1 nonzero per warp, 16384 blocks x 256 threads, full occupancy.
//   Explicit 6x LDG.E.128 front-batch (MLP=6/warp), evict-first stores.
// Measured across the session: 107.8-108.8us, DRAM 78.5-79.4% — the
// mixed read/write HBM3e saturation ceiling for this compulsory-traffic
// gather (403MB writes + ~237MB deduped reads). Deeper MLP, lower/higher
// occupancy, persistent grids, and cache-policy variants all measured
// equal-or-worse.
__global__ __launch_bounds__(THREADS)
void gather_scale_kernel(const float4* __restrict__ W,      // [N_LAYERS*D_SAE, 192]
                         const float*  __restrict__ vals,   // [NNZ]
                         const int*    __restrict__ lidx,   // [NNZ]
                         const int*    __restrict__ fidx,   // [NNZ]
                         float4*       __restrict__ out)    // [NNZ, 192]
{
    const int warp_in_blk = threadIdx.x >> 5;
    const int lane        = threadIdx.x & 31;
    const int nz          = blockIdx.x * WARPS_PER_BLOCK + warp_in_blk;
    if (nz >= NNZ) return;

    const float v = __ldg(&vals[nz]);
    const long  row = (long)__ldg(&lidx[nz]) * D_SAE + (long)__ldg(&fidx[nz]);

    const float4* __restrict__ src = W   + row * (long)VEC;
    float4*       __restrict__ dst = out + (long)nz * (long)VEC;

    // Explicit front-batch: all 6 independent LDG.E.128 into distinct
    // registers before any store — guarantees per-warp read MLP=6 (regs=32
    // in SASS is the tell that ptxas preserved the batch).
    float4 a[VEC / 32];
    #pragma unroll
    for (int i = 0; i < VEC / 32; ++i)
        a[i] = __ldg(&src[lane + i * 32]);

    // Scale + evict-first stores (output stream is never re-read).
    #pragma unroll
    for (int i = 0; i < VEC / 32; ++i) {
        a[i].x *= v; a[i].y *= v; a[i].z *= v; a[i].w *= v;
        __stcs(&dst[lane + i * 32], a[i]);
    }
}

extern "C" void kernel_launch(void* const* d_in, const int* in_sizes, int n_in,
                              void* d_out, int out_size)
{
    // metadata order: W_D (f32), values (f32), layer_idx (i32), pos_idx (i32), feat_idx (i32)
    const float4* W    = (const float4*)d_in[0];
    const float*  vals = (const float*)d_in[1];
    const int*    lidx = (const int*)d_in[2];
    // pos_idx (d_in[3]) is unused by the reference computation
    const int*    fidx = (const int*)d_in[4];
    float4*       out  = (float4*)d_out;

    const int grid = NNZ / WARPS_PER_BLOCK;   // 16384 blocks
    gather_scale_kernel<<<grid, THREADS>>>(W, vals, lidx, fidx, out);
}